// round 12
// baseline (speedup 1.0000x reference)
#include <cuda_runtime.h>

// Fixed problem shape
#define NMOL   256
#define NATOM  512
#define KNB    32
#define NTOT   (NMOL * NATOM)            // 131072 atoms
#define EDG    ((size_t)NTOT * KNB)      // 4194304 edges
#define TPB    128                       // 1 thread per atom
#define ACCB   0x3F7FFFFFu               // (b-1) < ACCB  <=>  0 < d2 < 1
#define SLO    128                       // KLO stride (u32 elems): conflict-free
#define SHI    130                       // KHI stride (u16 elems): bank=(q+tid/2)%32,
                                         // conflict-free for divergent q (65%32==1)
typedef unsigned long long u64;
typedef unsigned int       u32;
typedef unsigned short     u16;

#define INFKEY 0x0000FFFFFFFFFFFFull     // hi=0xFFFF lo=0xFFFFFFFF; real keys < 2^39

// smem: klo u32[33*SLO]=16896 + khi u16[33*SHI]=8580 pad->8592 (16B align for the
// u64 position views) + positions 6144 = 31632 B -> 7 blocks/SM, grid 1024: 1 wave.
#define KLO_BYTES (33 * SLO * 4)
#define KHI_BYTES (((33 * SHI * 2) + 15) & ~15)
#define SMEM_BYTES (KLO_BYTES + KHI_BYTES + NATOM * 12)

__device__ __forceinline__ u64 pk2(u32 lo, u32 hi) {
    u64 r; asm("mov.b64 %0, {%1, %2};" : "=l"(r) : "r"(lo), "r"(hi)); return r;
}
__device__ __forceinline__ void upk2(u64 v, u32& lo, u32& hi) {
    asm("mov.b64 {%0, %1}, %2;" : "=r"(lo), "=r"(hi) : "l"(v));
}
__device__ __forceinline__ u64 addx2(u64 a, u64 b) {
    u64 r; asm("add.rn.f32x2 %0, %1, %2;" : "=l"(r) : "l"(a), "l"(b)); return r;
}
__device__ __forceinline__ u64 mulx2(u64 a, u64 b) {
    u64 r; asm("mul.rn.f32x2 %0, %1, %2;" : "=l"(r) : "l"(a), "l"(b)); return r;
}
__device__ __forceinline__ float sqrt_ap(float v) {
    float r; asm("sqrt.approx.f32 %0, %1;" : "=f"(r) : "f"(v)); return r;
}

// Strided heap slots (conflict-free for both uniform and divergent q).
#define HLO(q) klo[(q) * SLO + tid]
#define HHI(q) khi[(q) * SHI + tid]

__device__ __forceinline__ u64 mk64(u32 lo, u32 hi) {
    return ((u64)hi << 32) | lo;                   // register pair: ~0-cost
}

// 4-ary max-heap sift-down, fixed size 32 (slot 32 = pad key 0, never wins).
// Depth <= 3, fully unrolled. Updates rootk when the root slot changes.
__device__ __forceinline__ void siftd(u32* klo, u16* khi, int tid,
                                      int p, u64 k, u64& rootk)
{
    if (p == 0) rootk = k;
    #pragma unroll
    for (int lvl = 0; lvl < 3; ++lvl) {
        const int l = 4 * p + 1;
        if (l > 31) break;                         // leaf
        const u64 c0 = mk64(HLO(l),     HHI(l));
        const u64 c1 = mk64(HLO(l + 1), HHI(l + 1));
        const u64 c2 = mk64(HLO(l + 2), HHI(l + 2));
        const u64 c3 = mk64(HLO(l + 3), HHI(l + 3)); // p==7 -> pad slot 32 (0)
        u64 a, b, m; int ai, bi, mi;
        if (c1 > c0) { a = c1; ai = l + 1; } else { a = c0; ai = l;     }
        if (c3 > c2) { b = c3; bi = l + 3; } else { b = c2; bi = l + 2; }
        if (b  > a ) { m = b;  mi = bi;    } else { m = a;  mi = ai;    }
        if (m <= k) break;
        HLO(p) = (u32)m; HHI(p) = (u16)(m >> 32);
        if (p == 0) rootk = m;
        p = mi;
    }
    HLO(p) = (u32)k; HHI(p) = (u16)(k >> 32);
}

// Stream one u64 remainder-mask word through the heap (replace-root when better).
__device__ __forceinline__ void stream_word(
    u32* klo, u16* khi, int tid, u64 m, int w,
    const float* sx, const float* sy, const float* sz,
    float nx, float ny, float nz, u64& rootk)
{
    #pragma unroll 1
    while (m) {
        const int b = __ffsll(m) - 1;
        m &= m - 1;
        const int j = (w << 6) + b;
        const float dx = __fadd_rn(sx[j], nx);     // bit-exact recompute
        const float dy = __fadd_rn(sy[j], ny);
        const float dz = __fadd_rn(sz[j], nz);
        const float d2 = __fadd_rn(__fadd_rn(__fmul_rn(dx, dx), __fmul_rn(dy, dy)),
                                   __fmul_rn(dz, dz));
        const u64 key = ((u64)__float_as_uint(d2) << 9) | (u32)j;
        if (key < rootk)
            siftd(klo, khi, tid, 0, key, rootk);
    }
}

__global__ void __launch_bounds__(TPB, 7)
topo_kernel(const float* __restrict__ x, float* __restrict__ out)
{
    extern __shared__ char dsm[];
    u32*   klo = (u32*)dsm;
    u16*   khi = (u16*)(dsm + KLO_BYTES);
    float* sx  = (float*)(dsm + KLO_BYTES + KHI_BYTES);   // 16B-aligned
    float* sy  = sx + NATOM;
    float* sz  = sy + NATOM;

    const int tid     = threadIdx.x;
    const int gatom   = blockIdx.x * TPB + tid;
    const int molbase = gatom & ~(NATOM - 1);
    const int i       = gatom & (NATOM - 1);

    for (int a = tid; a < NATOM; a += TPB) {
        const float* p = x + (size_t)(molbase + a) * 3;
        sx[a] = p[0]; sy[a] = p[1]; sz[a] = p[2];
    }
    __syncthreads();

    const float px = sx[i], py = sy[i], pz = sz[i];
    const float nx = -px,   ny = -py,   nz = -pz;
    const u64 npx = pk2(__float_as_uint(nx), __float_as_uint(nx));
    const u64 npy = pk2(__float_as_uint(ny), __float_as_uint(ny));
    const u64 npz = pk2(__float_as_uint(nz), __float_as_uint(nz));

    const u64* sx2 = reinterpret_cast<const u64*>(sx);
    const u64* sy2 = reinterpret_cast<const u64*>(sy);
    const u64* sz2 = reinterpret_cast<const u64*>(sz);

    // ---- Heap prefill: all 32 slots INF (covers lanes with <32 accepts). ----
    #pragma unroll
    for (int q = 0; q < 32; ++q) { HLO(q) = 0xFFFFFFFFu; HHI(q) = 0xFFFFu; }
    HLO(32) = 0; HHI(32) = 0;                      // pad child: never promoted

    // ---- Phase 1 (fused fill): distances 2-at-a-time (bit-exact RN).
    //      First 32 accepts append straight into heap slots (d2 NOT recomputed);
    //      accepts beyond 32 set bits in the remainder mask. ----
    u64 mrem[8];
    int hc = 0;

    #pragma unroll 1
    for (int w = 0; w < 8; ++w) {
        u64 mw = 0;
        #pragma unroll
        for (int s = 0; s < 32; ++s) {
            const int t  = w * 32 + s;
            const u64 dx = addx2(sx2[t], npx);
            const u64 dy = addx2(sy2[t], npy);
            const u64 dz = addx2(sz2[t], npz);
            const u64 d2 = addx2(addx2(mulx2(dx, dx), mulx2(dy, dy)), mulx2(dz, dz));
            u32 b0, b1; upk2(d2, b0, b1);
            if (b0 - 1u < ACCB) {                  // 0 < d2 < 1
                if (hc < 32) {
                    const u64 key = ((u64)b0 << 9) | (u32)((w << 6) + 2 * s);
                    HLO(hc) = (u32)key; HHI(hc) = (u16)(key >> 32);
                    ++hc;
                } else mw |= 1ull << (2 * s);
            }
            if (b1 - 1u < ACCB) {
                if (hc < 32) {
                    const u64 key = ((u64)b1 << 9) | (u32)((w << 6) + 2 * s + 1);
                    HLO(hc) = (u32)key; HHI(hc) = (u16)(key >> 32);
                    ++hc;
                } else mw |= 2ull << (2 * s);
            }
        }
        mrem[w] = mw;
    }

    // ---- Floyd heapify: uniform 8 sift-downs (4-ary, depth <= 3). ----
    u64 rootk = INFKEY;
    #pragma unroll 1
    for (int p = 7; p >= 0; --p)
        siftd(klo, khi, tid, p, mk64(HLO(p), HHI(p)), rootk);

    // ---- Stage B: stream remainder candidates (replace-root). ----
    #pragma unroll 1
    for (int w = 0; w < 8; ++w)
        stream_word(klo, khi, tid, mrem[w], w, sx, sy, sz, nx, ny, nz, rootk);

    // ---- Heapsort: 31 uniform pops (INF keys land in the tail slots),
    //      leaves slots 0..31 ascending by (d2bits, j). ----
    #pragma unroll 1
    for (int size = 31; size >= 1; --size) {
        const u64 top = mk64(HLO(0), HHI(0));
        u64 k = mk64(HLO(size), HHI(size));
        HLO(size) = (u32)top; HHI(size) = (u16)(top >> 32);
        int p = 0;
        #pragma unroll
        for (int lvl = 0; lvl < 3; ++lvl) {
            const int l = 4 * p + 1;
            if (l >= size) break;
            const u64 c0 = mk64(HLO(l), HHI(l));
            const u64 c1 = (l + 1 < size) ? mk64(HLO(l + 1), HHI(l + 1)) : 0;
            const u64 c2 = (l + 2 < size) ? mk64(HLO(l + 2), HHI(l + 2)) : 0;
            const u64 c3 = (l + 3 < size) ? mk64(HLO(l + 3), HHI(l + 3)) : 0;
            u64 a, b, m; int ai, bi, mi;
            if (c1 > c0) { a = c1; ai = l + 1; } else { a = c0; ai = l;     }
            if (c3 > c2) { b = c3; bi = l + 3; } else { b = c2; bi = l + 2; }
            if (b  > a ) { m = b;  mi = bi;    } else { m = a;  mi = ai;    }
            if (m <= k) break;
            HLO(p) = (u32)m; HHI(p) = (u16)(m >> 32);
            p = mi;
        }
        HLO(p) = (u32)k; HHI(p) = (u16)(k >> 32);
    }

    // ---- Phase 3: emit, per-atom contiguous -> all float4 stores. ----
    float* obi  = out + (size_t)gatom * KNB;
    float* obj  = out + EDG + (size_t)gatom * KNB;
    float* ovec = out + 2 * EDG + (size_t)gatom * (3 * KNB);
    float* odst = out + 5 * EDG + (size_t)gatom * KNB;
    float* oval = out + 6 * EDG + (size_t)gatom * KNB;

    const float fgi = (float)gatom;

    #pragma unroll
    for (int qb = 0; qb < KNB / 4; ++qb) {
        float bi4[4], bj4[4], dd4[4], vv4[4], vec12[12];
        #pragma unroll
        for (int u = 0; u < 4; ++u) {
            const int  s   = qb * 4 + u;
            const u32  lo  = HLO(s);
            const u32  hi  = HHI(s);
            const u64  key = mk64(lo, hi);
            const bool ok  = key < (1ull << 40);   // real keys < 2^39
            const int  j   = (int)(lo & 511u);     // INF lo -> 511: safe index
            const u32  d2b = (u32)(key >> 9);
            const float dx = __fadd_rn(sx[j], nx);
            const float dy = __fadd_rn(sy[j], ny);
            const float dz = __fadd_rn(sz[j], nz);
            vec12[u * 3 + 0] = ok ? dx : 0.0f;
            vec12[u * 3 + 1] = ok ? dy : 0.0f;
            vec12[u * 3 + 2] = ok ? dz : 0.0f;
            bi4[u] = ok ? fgi : -1.0f;
            bj4[u] = ok ? (float)(molbase + j) : -1.0f;
            dd4[u] = ok ? sqrt_ap(__uint_as_float(d2b)) : 0.0f;
            vv4[u] = ok ? 1.0f : 0.0f;
        }
        *(float4*)(obi  + qb * 4)      = make_float4(bi4[0], bi4[1], bi4[2], bi4[3]);
        *(float4*)(obj  + qb * 4)      = make_float4(bj4[0], bj4[1], bj4[2], bj4[3]);
        *(float4*)(odst + qb * 4)      = make_float4(dd4[0], dd4[1], dd4[2], dd4[3]);
        *(float4*)(oval + qb * 4)      = make_float4(vv4[0], vv4[1], vv4[2], vv4[3]);
        *(float4*)(ovec + qb * 12 + 0) = make_float4(vec12[0], vec12[1], vec12[2],  vec12[3]);
        *(float4*)(ovec + qb * 12 + 4) = make_float4(vec12[4], vec12[5], vec12[6],  vec12[7]);
        *(float4*)(ovec + qb * 12 + 8) = make_float4(vec12[8], vec12[9], vec12[10], vec12[11]);
    }
}

extern "C" void kernel_launch(void* const* d_in, const int* in_sizes, int n_in,
                              void* d_out, int out_size)
{
    const float* x   = (const float*)d_in[0];
    float*       out = (float*)d_out;

    cudaFuncSetAttribute(topo_kernel, cudaFuncAttributeMaxDynamicSharedMemorySize,
                         SMEM_BYTES);
    topo_kernel<<<NTOT / TPB, TPB, SMEM_BYTES>>>(x, out);
}

// round 13
// speedup vs baseline: 1.0572x; 1.0572x over previous
#include <cuda_runtime.h>

// Fixed problem shape
#define NMOL   256
#define NATOM  512
#define KNB    32
#define NTOT   (NMOL * NATOM)            // 131072 atoms
#define EDG    ((size_t)NTOT * KNB)      // 4194304 edges
#define TPB    128                       // 1 thread per atom
#define INFK32 0xFFFFFFFFu
#define ACCB   0x3F7FFFFFu               // (b-1) < ACCB  <=>  0 < d2 < 1
#define SLO    128                       // HK stride (u32): bank=tid%32, conflict-free
#define SHI    130                       // HJ stride (u16): bank=(q+tid/2)%32,
                                         // conflict-free for divergent q (65%32==1)
typedef unsigned long long u64;
typedef unsigned int       u32;
typedef unsigned short     u16;

// smem: hk u32[33*SLO]=16896 + hj u16[33*SHI]=8580 pad->8592 (16B align) + pos 6144
// = 31632 B -> 7 blocks/SM, grid 1024 over 1036 slots: 1 wave, 1.2% imbalance.
#define HK_BYTES (33 * SLO * 4)
#define HJ_BYTES (((33 * SHI * 2) + 15) & ~15)
#define SMEM_BYTES (HK_BYTES + HJ_BYTES + NATOM * 12)

__device__ __forceinline__ u64 pk2(u32 lo, u32 hi) {
    u64 r; asm("mov.b64 %0, {%1, %2};" : "=l"(r) : "r"(lo), "r"(hi)); return r;
}
__device__ __forceinline__ void upk2(u64 v, u32& lo, u32& hi) {
    asm("mov.b64 {%0, %1}, %2;" : "=r"(lo), "=r"(hi) : "l"(v));
}
__device__ __forceinline__ u64 addx2(u64 a, u64 b) {
    u64 r; asm("add.rn.f32x2 %0, %1, %2;" : "=l"(r) : "l"(a), "l"(b)); return r;
}
__device__ __forceinline__ u64 mulx2(u64 a, u64 b) {
    u64 r; asm("mul.rn.f32x2 %0, %1, %2;" : "=l"(r) : "l"(a), "l"(b)); return r;
}
__device__ __forceinline__ float sqrt_ap(float v) {
    float r; asm("sqrt.approx.f32 %0, %1;" : "=f"(r) : "f"(v)); return r;
}

// Exact lexicographic (d2bits, j) order == lax.top_k order (asc d2, then asc j).
__device__ __forceinline__ bool ltp(u32 ka, u32 ja, u32 kb, u32 jb) {
    return (ka < kb) || (ka == kb && ja < jb);
}
__device__ __forceinline__ bool gtp(u32 ka, u32 ja, u32 kb, u32 jb) {
    return (ka > kb) || (ka == kb && ja > jb);
}

// Strided heap slots (conflict-free for both uniform and divergent q).
#define HK(q) hk[(q) * SLO + tid]
#define HJ(q) hj[(q) * SHI + tid]

// 4-ary max-heap sift-down, fixed size 32 (slot 32 = pad (0,0), never wins).
// Depth <= 3: fully unrolled. Updates (rk, rj) when the root slot changes.
__device__ __forceinline__ void siftd(u32* hk, u16* hj, int tid,
                                      int p, u32 k, u32 j, u32& rk, u32& rj)
{
    if (p == 0) { rk = k; rj = j; }               // provisional root
    #pragma unroll
    for (int lvl = 0; lvl < 3; ++lvl) {
        const int l = 4 * p + 1;
        if (l > 31) break;                        // leaf
        const u32 k0 = HK(l),     j0 = HJ(l);
        const u32 k1 = HK(l + 1), j1 = HJ(l + 1);
        const u32 k2 = HK(l + 2), j2 = HJ(l + 2);
        const u32 k3 = HK(l + 3), j3 = HJ(l + 3); // p==7 -> slot 32 pad (0,0)
        u32 ak, aj, bk, bj; int ai, bi;
        if (gtp(k1, j1, k0, j0)) { ak = k1; aj = j1; ai = l + 1; }
        else                     { ak = k0; aj = j0; ai = l;     }
        if (gtp(k3, j3, k2, j2)) { bk = k3; bj = j3; bi = l + 3; }
        else                     { bk = k2; bj = j2; bi = l + 2; }
        u32 mk, mj; int mi;
        if (gtp(bk, bj, ak, aj)) { mk = bk; mj = bj; mi = bi; }
        else                     { mk = ak; mj = aj; mi = ai; }
        if (!gtp(mk, mj, k, j)) break;
        HK(p) = mk; HJ(p) = (u16)mj;
        if (p == 0) { rk = mk; rj = mj; }
        p = mi;
    }
    HK(p) = k; HJ(p) = (u16)j;
}

// Stream one u64 mask word through the full heap (replace-root when better).
__device__ __forceinline__ void stream_word(
    u32* hk, u16* hj, int tid, u64 m, int w,
    const float* sx, const float* sy, const float* sz,
    float nx, float ny, float nz, u32& rk, u32& rj)
{
    #pragma unroll 1
    while (m) {
        const int b = __ffsll(m) - 1;
        m &= m - 1;
        const int j = (w << 6) + b;
        const float dx = __fadd_rn(sx[j], nx);    // bit-exact recompute
        const float dy = __fadd_rn(sy[j], ny);
        const float dz = __fadd_rn(sz[j], nz);
        const float d2 = __fadd_rn(__fadd_rn(__fmul_rn(dx, dx), __fmul_rn(dy, dy)),
                                   __fmul_rn(dz, dz));
        const u32 kb = __float_as_uint(d2);
        if (ltp(kb, (u32)j, rk, rj))
            siftd(hk, hj, tid, 0, kb, (u32)j, rk, rj);
    }
}

__global__ void __launch_bounds__(TPB, 7)
topo_kernel(const float* __restrict__ x, float* __restrict__ out)
{
    extern __shared__ char dsm[];
    u32*   hk = (u32*)dsm;
    u16*   hj = (u16*)(dsm + HK_BYTES);
    float* sx = (float*)(dsm + HK_BYTES + HJ_BYTES);    // 16B-aligned
    float* sy = sx + NATOM;
    float* sz = sy + NATOM;

    const int tid     = threadIdx.x;
    const int gatom   = blockIdx.x * TPB + tid;
    const int molbase = gatom & ~(NATOM - 1);
    const int i       = gatom & (NATOM - 1);

    for (int a = tid; a < NATOM; a += TPB) {
        const float* p = x + (size_t)(molbase + a) * 3;
        sx[a] = p[0]; sy[a] = p[1]; sz[a] = p[2];
    }
    __syncthreads();

    const float px = sx[i], py = sy[i], pz = sz[i];
    const float nx = -px,   ny = -py,   nz = -pz;
    const u64 npx = pk2(__float_as_uint(nx), __float_as_uint(nx));
    const u64 npy = pk2(__float_as_uint(ny), __float_as_uint(ny));
    const u64 npz = pk2(__float_as_uint(nz), __float_as_uint(nz));

    const u64* sx2 = reinterpret_cast<const u64*>(sx);
    const u64* sy2 = reinterpret_cast<const u64*>(sy);
    const u64* sz2 = reinterpret_cast<const u64*>(sz);

    // ---- Phase 1: PURE distance pass, 2-at-a-time (bit-exact RN);
    //      single accept mask (0 < d2 < 1). No heap work in here. ----
    u64 macc[8];

    #pragma unroll 1
    for (int w = 0; w < 8; ++w) {
        u64 ma = 0;
        #pragma unroll
        for (int s = 0; s < 32; ++s) {
            const int t  = w * 32 + s;
            const u64 dx = addx2(sx2[t], npx);
            const u64 dy = addx2(sy2[t], npy);
            const u64 dz = addx2(sz2[t], npz);
            const u64 d2 = addx2(addx2(mulx2(dx, dx), mulx2(dy, dy)), mulx2(dz, dz));
            u32 b0, b1; upk2(d2, b0, b1);
            if (b0 - 1u < ACCB) ma |= (1ull << (2 * s));
            if (b1 - 1u < ACCB) ma |= (2ull << (2 * s));
        }
        macc[w] = ma;
    }

    // ---- Heap prefill (INFK32 = invalid; lanes with <32 accepts keep some) ----
    #pragma unroll
    for (int q = 0; q < 32; ++q) { HK(q) = INFK32; HJ(q) = 0xFFFFu; }
    HK(32) = 0; HJ(32) = 0;                       // pad child: never promoted

    // ---- Stage A: append-only fill of the first 32 accepts. ----
    int hc = 0;
    int wr = 8; u64 mr = 0;                       // resume point

    #pragma unroll 1
    for (int w = 0; w < 8; ++w) {
        u64 m = macc[w];
        #pragma unroll 1
        while (m && hc < 32) {
            const int b = __ffsll(m) - 1;
            m &= m - 1;
            const int j = (w << 6) + b;
            const float dx = __fadd_rn(sx[j], nx);
            const float dy = __fadd_rn(sy[j], ny);
            const float dz = __fadd_rn(sz[j], nz);
            const float d2 = __fadd_rn(__fadd_rn(__fmul_rn(dx, dx), __fmul_rn(dy, dy)),
                                       __fmul_rn(dz, dz));
            HK(hc) = __float_as_uint(d2); HJ(hc) = (u16)j;
            ++hc;
        }
        if (m) { wr = w; mr = m; break; }         // heap filled, bits remain
    }

    // ---- Floyd heapify: uniform 8 sift-downs (4-ary, depth <= 3) ----
    u32 rk = INFK32, rj = 0xFFFFu;
    #pragma unroll 1
    for (int p = 7; p >= 0; --p)
        siftd(hk, hj, tid, p, HK(p), HJ(p), rk, rj);  // p==0 call yields true root

    // ---- Stage B: stream remaining accepts (replace-root when better). ----
    if (wr < 8) {
        stream_word(hk, hj, tid, mr, wr, sx, sy, sz, nx, ny, nz, rk, rj);
        #pragma unroll 1
        for (int w = wr + 1; w < 8; ++w)
            stream_word(hk, hj, tid, macc[w], w, sx, sy, sz, nx, ny, nz, rk, rj);
    }

    // ---- Heapsort: 31 uniform pops (INFK32s land in the tail slots),
    //      leaves slots 0..31 ascending by (d2bits, j). ----
    #pragma unroll 1
    for (int size = 31; size >= 1; --size) {
        const u32 tk = HK(0); const u32 tj = HJ(0);
        u32 k = HK(size), j = HJ(size);
        HK(size) = tk; HJ(size) = (u16)tj;
        int p = 0;
        #pragma unroll
        for (int lvl = 0; lvl < 3; ++lvl) {
            const int l = 4 * p + 1;
            if (l >= size) break;
            const u32 k0 = HK(l),                          j0 = HJ(l);
            const u32 k1 = (l + 1 < size) ? HK(l + 1) : 0, j1 = (l + 1 < size) ? HJ(l + 1) : 0;
            const u32 k2 = (l + 2 < size) ? HK(l + 2) : 0, j2 = (l + 2 < size) ? HJ(l + 2) : 0;
            const u32 k3 = (l + 3 < size) ? HK(l + 3) : 0, j3 = (l + 3 < size) ? HJ(l + 3) : 0;
            u32 ak, aj, bk, bj; int ai, bi;
            if (gtp(k1, j1, k0, j0)) { ak = k1; aj = j1; ai = l + 1; }
            else                     { ak = k0; aj = j0; ai = l;     }
            if (gtp(k3, j3, k2, j2)) { bk = k3; bj = j3; bi = l + 3; }
            else                     { bk = k2; bj = j2; bi = l + 2; }
            u32 mk, mj; int mi;
            if (gtp(bk, bj, ak, aj)) { mk = bk; mj = bj; mi = bi; }
            else                     { mk = ak; mj = aj; mi = ai; }
            if (!gtp(mk, mj, k, j)) break;
            HK(p) = mk; HJ(p) = (u16)mj;
            p = mi;
        }
        HK(p) = k; HJ(p) = (u16)j;
    }

    // ---- Phase 3: emit, per-atom contiguous -> all float4 stores. ----
    float* obi  = out + (size_t)gatom * KNB;
    float* obj  = out + EDG + (size_t)gatom * KNB;
    float* ovec = out + 2 * EDG + (size_t)gatom * (3 * KNB);
    float* odst = out + 5 * EDG + (size_t)gatom * KNB;
    float* oval = out + 6 * EDG + (size_t)gatom * KNB;

    const float fgi = (float)gatom;

    #pragma unroll
    for (int qb = 0; qb < KNB / 4; ++qb) {
        float bi4[4], bj4[4], dd4[4], vv4[4], vec12[12];
        #pragma unroll
        for (int u = 0; u < 4; ++u) {
            const int  s   = qb * 4 + u;
            const u32  d2b = HK(s);
            const bool ok  = (d2b != INFK32);     // real keys <= 0x3F7FFFFF
            const int  j   = (int)HJ(s) & (NATOM - 1);
            const float dx = __fadd_rn(sx[j], nx);
            const float dy = __fadd_rn(sy[j], ny);
            const float dz = __fadd_rn(sz[j], nz);
            vec12[u * 3 + 0] = ok ? dx : 0.0f;
            vec12[u * 3 + 1] = ok ? dy : 0.0f;
            vec12[u * 3 + 2] = ok ? dz : 0.0f;
            bi4[u] = ok ? fgi : -1.0f;
            bj4[u] = ok ? (float)(molbase + j) : -1.0f;
            dd4[u] = ok ? sqrt_ap(__uint_as_float(d2b)) : 0.0f;
            vv4[u] = ok ? 1.0f : 0.0f;
        }
        *(float4*)(obi  + qb * 4)      = make_float4(bi4[0], bi4[1], bi4[2], bi4[3]);
        *(float4*)(obj  + qb * 4)      = make_float4(bj4[0], bj4[1], bj4[2], bj4[3]);
        *(float4*)(odst + qb * 4)      = make_float4(dd4[0], dd4[1], dd4[2], dd4[3]);
        *(float4*)(oval + qb * 4)      = make_float4(vv4[0], vv4[1], vv4[2], vv4[3]);
        *(float4*)(ovec + qb * 12 + 0) = make_float4(vec12[0], vec12[1], vec12[2],  vec12[3]);
        *(float4*)(ovec + qb * 12 + 4) = make_float4(vec12[4], vec12[5], vec12[6],  vec12[7]);
        *(float4*)(ovec + qb * 12 + 8) = make_float4(vec12[8], vec12[9], vec12[10], vec12[11]);
    }
}

extern "C" void kernel_launch(void* const* d_in, const int* in_sizes, int n_in,
                              void* d_out, int out_size)
{
    const float* x   = (const float*)d_in[0];
    float*       out = (float*)d_out;

    cudaFuncSetAttribute(topo_kernel, cudaFuncAttributeMaxDynamicSharedMemorySize,
                         SMEM_BYTES);
    topo_kernel<<<NTOT / TPB, TPB, SMEM_BYTES>>>(x, out);
}

// round 14
// speedup vs baseline: 1.1120x; 1.0518x over previous
#include <cuda_runtime.h>

// Fixed problem shape
#define NMOL   256
#define NATOM  512
#define KNB    32
#define NTOT   (NMOL * NATOM)            // 131072 atoms
#define EDG    ((size_t)NTOT * KNB)      // 4194304 edges
#define TPB    128                       // 1 thread per atom
#define INFK32 0xFFFFFFFFu
#define ACCB   0x3F7FFFFFu               // (b-1) < ACCB  <=>  0 < d2 < 1
#define LOB    0x3F199999u               // (b-1) < LOB   <=>  0 < d2 < 0.6f
#define HISKIP 0x3F19999Au               // root k below this => no hi key can enter
#define SLO    128                       // HK stride (u32): bank=tid%32, conflict-free
#define SHI    130                       // HJ stride (u16): bank=(q+tid/2)%32,
                                         // conflict-free for divergent q (65%32==1)
typedef unsigned long long u64;
typedef unsigned int       u32;
typedef unsigned short     u16;

// smem: hk u32[33*SLO]=16896 + hj u16[33*SHI]=8580 pad->8592 (16B align) + pos 6144
// = 31632 B -> 7 blocks/SM, grid 1024 over 1036 slots: 1 wave, 1.2% imbalance.
#define HK_BYTES (33 * SLO * 4)
#define HJ_BYTES (((33 * SHI * 2) + 15) & ~15)
#define SMEM_BYTES (HK_BYTES + HJ_BYTES + NATOM * 12)

__device__ __forceinline__ u64 pk2(u32 lo, u32 hi) {
    u64 r; asm("mov.b64 %0, {%1, %2};" : "=l"(r) : "r"(lo), "r"(hi)); return r;
}
__device__ __forceinline__ void upk2(u64 v, u32& lo, u32& hi) {
    asm("mov.b64 {%0, %1}, %2;" : "=r"(lo), "=r"(hi) : "l"(v));
}
__device__ __forceinline__ u64 addx2(u64 a, u64 b) {
    u64 r; asm("add.rn.f32x2 %0, %1, %2;" : "=l"(r) : "l"(a), "l"(b)); return r;
}
__device__ __forceinline__ u64 mulx2(u64 a, u64 b) {
    u64 r; asm("mul.rn.f32x2 %0, %1, %2;" : "=l"(r) : "l"(a), "l"(b)); return r;
}
__device__ __forceinline__ float sqrt_ap(float v) {
    float r; asm("sqrt.approx.f32 %0, %1;" : "=f"(r) : "f"(v)); return r;
}

// Exact lexicographic (d2bits, j) order == lax.top_k order (asc d2, then asc j).
__device__ __forceinline__ bool ltp(u32 ka, u32 ja, u32 kb, u32 jb) {
    return (ka < kb) || (ka == kb && ja < jb);
}
__device__ __forceinline__ bool gtp(u32 ka, u32 ja, u32 kb, u32 jb) {
    return (ka > kb) || (ka == kb && ja > jb);
}

// Strided heap slots (conflict-free for both uniform and divergent q).
#define HK(q) hk[(q) * SLO + tid]
#define HJ(q) hj[(q) * SHI + tid]

// 4-ary max-heap sift-down, fixed size 32 (slot 32 = pad (0,0), never wins).
// Depth <= 3: fully unrolled. Updates (rk, rj) when the root slot changes.
__device__ __forceinline__ void siftd(u32* hk, u16* hj, int tid,
                                      int p, u32 k, u32 j, u32& rk, u32& rj)
{
    if (p == 0) { rk = k; rj = j; }               // provisional root
    #pragma unroll
    for (int lvl = 0; lvl < 3; ++lvl) {
        const int l = 4 * p + 1;
        if (l > 31) break;                        // leaf
        const u32 k0 = HK(l),     j0 = HJ(l);
        const u32 k1 = HK(l + 1), j1 = HJ(l + 1);
        const u32 k2 = HK(l + 2), j2 = HJ(l + 2);
        const u32 k3 = HK(l + 3), j3 = HJ(l + 3); // p==7 -> slot 32 pad (0,0)
        u32 ak, aj, bk, bj; int ai, bi;
        if (gtp(k1, j1, k0, j0)) { ak = k1; aj = j1; ai = l + 1; }
        else                     { ak = k0; aj = j0; ai = l;     }
        if (gtp(k3, j3, k2, j2)) { bk = k3; bj = j3; bi = l + 3; }
        else                     { bk = k2; bj = j2; bi = l + 2; }
        u32 mk, mj; int mi;
        if (gtp(bk, bj, ak, aj)) { mk = bk; mj = bj; mi = bi; }
        else                     { mk = ak; mj = aj; mi = ai; }
        if (!gtp(mk, mj, k, j)) break;
        HK(p) = mk; HJ(p) = (u16)mj;
        if (p == 0) { rk = mk; rj = mj; }
        p = mi;
    }
    HK(p) = k; HJ(p) = (u16)j;
}

// Stream one u64 mask word through the full heap (replace-root when better).
__device__ __forceinline__ void stream_word(
    u32* hk, u16* hj, int tid, u64 m, int w,
    const float* sx, const float* sy, const float* sz,
    float nx, float ny, float nz, u32& rk, u32& rj)
{
    #pragma unroll 1
    while (m) {
        const int b = __ffsll(m) - 1;
        m &= m - 1;
        const int j = (w << 6) + b;
        const float dx = __fadd_rn(sx[j], nx);    // bit-exact recompute
        const float dy = __fadd_rn(sy[j], ny);
        const float dz = __fadd_rn(sz[j], nz);
        const float d2 = __fadd_rn(__fadd_rn(__fmul_rn(dx, dx), __fmul_rn(dy, dy)),
                                   __fmul_rn(dz, dz));
        const u32 kb = __float_as_uint(d2);
        if (ltp(kb, (u32)j, rk, rj))
            siftd(hk, hj, tid, 0, kb, (u32)j, rk, rj);
    }
}

__global__ void __launch_bounds__(TPB, 7)
topo_kernel(const float* __restrict__ x, float* __restrict__ out)
{
    extern __shared__ char dsm[];
    u32*   hk = (u32*)dsm;
    u16*   hj = (u16*)(dsm + HK_BYTES);
    float* sx = (float*)(dsm + HK_BYTES + HJ_BYTES);    // 16B-aligned
    float* sy = sx + NATOM;
    float* sz = sy + NATOM;

    const int tid     = threadIdx.x;
    const int gatom   = blockIdx.x * TPB + tid;
    const int molbase = gatom & ~(NATOM - 1);
    const int i       = gatom & (NATOM - 1);

    for (int a = tid; a < NATOM; a += TPB) {
        const float* p = x + (size_t)(molbase + a) * 3;
        sx[a] = p[0]; sy[a] = p[1]; sz[a] = p[2];
    }
    __syncthreads();

    const float px = sx[i], py = sy[i], pz = sz[i];
    const float nx = -px,   ny = -py,   nz = -pz;
    const u64 npx = pk2(__float_as_uint(nx), __float_as_uint(nx));
    const u64 npy = pk2(__float_as_uint(ny), __float_as_uint(ny));
    const u64 npz = pk2(__float_as_uint(nz), __float_as_uint(nz));

    const u64* sx2 = reinterpret_cast<const u64*>(sx);
    const u64* sy2 = reinterpret_cast<const u64*>(sy);
    const u64* sz2 = reinterpret_cast<const u64*>(sz);

    // ---- Phase 1: distances 2-at-a-time (bit-exact RN). u64 masks:
    //      mlo = near accepts (0<d2<0.6), mhi = far accepts (0.6<=d2<1). ----
    u64 mlo8[8], mhi8[8];

    #pragma unroll 1
    for (int w = 0; w < 8; ++w) {
        u64 ma = 0, ml = 0;
        #pragma unroll
        for (int s = 0; s < 32; ++s) {
            const int t  = w * 32 + s;
            const u64 dx = addx2(sx2[t], npx);
            const u64 dy = addx2(sy2[t], npy);
            const u64 dz = addx2(sz2[t], npz);
            const u64 d2 = addx2(addx2(mulx2(dx, dx), mulx2(dy, dy)), mulx2(dz, dz));
            u32 b0, b1; upk2(d2, b0, b1);
            if (b0 - 1u < ACCB) ma |= (1ull << (2 * s));
            if (b1 - 1u < ACCB) ma |= (2ull << (2 * s));
            if (b0 - 1u < LOB)  ml |= (1ull << (2 * s));
            if (b1 - 1u < LOB)  ml |= (2ull << (2 * s));
        }
        mhi8[w] = ma ^ ml;
        mlo8[w] = ml;
    }

    // ---- Heap prefill (INFK32 = invalid; lanes with <32 neighbors keep some) ----
    #pragma unroll
    for (int q = 0; q < 32; ++q) { HK(q) = INFK32; HJ(q) = 0xFFFFu; }
    HK(32) = 0; HJ(32) = 0;                       // pad child: never promoted

    // ---- Stage A: append-only fill, near candidates first, then far. ----
    int hc = 0;
    int wr = 8; u64 mr = 0;                       // lo resume point
    int wh = 8; u64 mh = 0;                       // hi resume point

    #pragma unroll 1
    for (int w = 0; w < 8; ++w) {
        u64 m = mlo8[w];
        #pragma unroll 1
        while (m && hc < 32) {
            const int b = __ffsll(m) - 1;
            m &= m - 1;
            const int j = (w << 6) + b;
            const float dx = __fadd_rn(sx[j], nx);
            const float dy = __fadd_rn(sy[j], ny);
            const float dz = __fadd_rn(sz[j], nz);
            const float d2 = __fadd_rn(__fadd_rn(__fmul_rn(dx, dx), __fmul_rn(dy, dy)),
                                       __fmul_rn(dz, dz));
            HK(hc) = __float_as_uint(d2); HJ(hc) = (u16)j;
            ++hc;
        }
        if (m) { wr = w; mr = m; break; }         // heap filled, lo bits remain
    }

    if (hc == 32) {
        wh = 0; mh = mhi8[0];                     // entire hi pass pending
    } else {
        #pragma unroll 1
        for (int w = 0; w < 8; ++w) {
            u64 m = mhi8[w];
            #pragma unroll 1
            while (m && hc < 32) {
                const int b = __ffsll(m) - 1;
                m &= m - 1;
                const int j = (w << 6) + b;
                const float dx = __fadd_rn(sx[j], nx);
                const float dy = __fadd_rn(sy[j], ny);
                const float dz = __fadd_rn(sz[j], nz);
                const float d2 = __fadd_rn(__fadd_rn(__fmul_rn(dx, dx), __fmul_rn(dy, dy)),
                                           __fmul_rn(dz, dz));
                HK(hc) = __float_as_uint(d2); HJ(hc) = (u16)j;
                ++hc;
            }
            if (m) { wh = w; mh = m; break; }
        }
    }

    // ---- Floyd heapify: uniform 8 sift-downs (4-ary, depth <= 3) ----
    u32 rk = INFK32, rj = 0xFFFFu;
    #pragma unroll 1
    for (int p = 7; p >= 0; --p)
        siftd(hk, hj, tid, p, HK(p), HJ(p), rk, rj);  // p==0 call yields true root

    // ---- Stage B: stream remainders. Near first; far pass skipped
    //      algebraically once rk < 0x3F19999A (no far key can beat root). ----
    if (wr < 8) {
        stream_word(hk, hj, tid, mr, wr, sx, sy, sz, nx, ny, nz, rk, rj);
        #pragma unroll 1
        for (int w = wr + 1; w < 8; ++w)
            stream_word(hk, hj, tid, mlo8[w], w, sx, sy, sz, nx, ny, nz, rk, rj);
    }
    if (wh < 8) {
        u64 m0 = (rk < HISKIP) ? 0ull : mh;
        stream_word(hk, hj, tid, m0, wh, sx, sy, sz, nx, ny, nz, rk, rj);
        #pragma unroll 1
        for (int w = wh + 1; w < 8; ++w) {
            u64 m = (rk < HISKIP) ? 0ull : mhi8[w];
            stream_word(hk, hj, tid, m, w, sx, sy, sz, nx, ny, nz, rk, rj);
        }
    }

    // ---- Heapsort: 31 uniform pops (INFK32s land in the tail slots),
    //      leaves slots 0..31 ascending by (d2bits, j). ----
    #pragma unroll 1
    for (int size = 31; size >= 1; --size) {
        const u32 tk = HK(0); const u32 tj = HJ(0);
        u32 k = HK(size), j = HJ(size);
        HK(size) = tk; HJ(size) = (u16)tj;
        int p = 0;
        #pragma unroll
        for (int lvl = 0; lvl < 3; ++lvl) {
            const int l = 4 * p + 1;
            if (l >= size) break;
            const u32 k0 = HK(l),                          j0 = HJ(l);
            const u32 k1 = (l + 1 < size) ? HK(l + 1) : 0, j1 = (l + 1 < size) ? HJ(l + 1) : 0;
            const u32 k2 = (l + 2 < size) ? HK(l + 2) : 0, j2 = (l + 2 < size) ? HJ(l + 2) : 0;
            const u32 k3 = (l + 3 < size) ? HK(l + 3) : 0, j3 = (l + 3 < size) ? HJ(l + 3) : 0;
            u32 ak, aj, bk, bj; int ai, bi;
            if (gtp(k1, j1, k0, j0)) { ak = k1; aj = j1; ai = l + 1; }
            else                     { ak = k0; aj = j0; ai = l;     }
            if (gtp(k3, j3, k2, j2)) { bk = k3; bj = j3; bi = l + 3; }
            else                     { bk = k2; bj = j2; bi = l + 2; }
            u32 mk, mj; int mi;
            if (gtp(bk, bj, ak, aj)) { mk = bk; mj = bj; mi = bi; }
            else                     { mk = ak; mj = aj; mi = ai; }
            if (!gtp(mk, mj, k, j)) break;
            HK(p) = mk; HJ(p) = (u16)mj;
            p = mi;
        }
        HK(p) = k; HJ(p) = (u16)j;
    }

    // ---- Phase 3: emit, per-atom contiguous -> all float4 stores. ----
    float* obi  = out + (size_t)gatom * KNB;
    float* obj  = out + EDG + (size_t)gatom * KNB;
    float* ovec = out + 2 * EDG + (size_t)gatom * (3 * KNB);
    float* odst = out + 5 * EDG + (size_t)gatom * KNB;
    float* oval = out + 6 * EDG + (size_t)gatom * KNB;

    const float fgi = (float)gatom;

    #pragma unroll
    for (int qb = 0; qb < KNB / 4; ++qb) {
        float bi4[4], bj4[4], dd4[4], vv4[4], vec12[12];
        #pragma unroll
        for (int u = 0; u < 4; ++u) {
            const int  s   = qb * 4 + u;
            const u32  d2b = HK(s);
            const bool ok  = (d2b != INFK32);     // real keys <= 0x3F7FFFFF
            const int  j   = (int)HJ(s) & (NATOM - 1);
            const float dx = __fadd_rn(sx[j], nx);
            const float dy = __fadd_rn(sy[j], ny);
            const float dz = __fadd_rn(sz[j], nz);
            vec12[u * 3 + 0] = ok ? dx : 0.0f;
            vec12[u * 3 + 1] = ok ? dy : 0.0f;
            vec12[u * 3 + 2] = ok ? dz : 0.0f;
            bi4[u] = ok ? fgi : -1.0f;
            bj4[u] = ok ? (float)(molbase + j) : -1.0f;
            dd4[u] = ok ? sqrt_ap(__uint_as_float(d2b)) : 0.0f;
            vv4[u] = ok ? 1.0f : 0.0f;
        }
        *(float4*)(obi  + qb * 4)      = make_float4(bi4[0], bi4[1], bi4[2], bi4[3]);
        *(float4*)(obj  + qb * 4)      = make_float4(bj4[0], bj4[1], bj4[2], bj4[3]);
        *(float4*)(odst + qb * 4)      = make_float4(dd4[0], dd4[1], dd4[2], dd4[3]);
        *(float4*)(oval + qb * 4)      = make_float4(vv4[0], vv4[1], vv4[2], vv4[3]);
        *(float4*)(ovec + qb * 12 + 0) = make_float4(vec12[0], vec12[1], vec12[2],  vec12[3]);
        *(float4*)(ovec + qb * 12 + 4) = make_float4(vec12[4], vec12[5], vec12[6],  vec12[7]);
        *(float4*)(ovec + qb * 12 + 8) = make_float4(vec12[8], vec12[9], vec12[10], vec12[11]);
    }
}

extern "C" void kernel_launch(void* const* d_in, const int* in_sizes, int n_in,
                              void* d_out, int out_size)
{
    const float* x   = (const float*)d_in[0];
    float*       out = (float*)d_out;

    cudaFuncSetAttribute(topo_kernel, cudaFuncAttributeMaxDynamicSharedMemorySize,
                         SMEM_BYTES);
    topo_kernel<<<NTOT / TPB, TPB, SMEM_BYTES>>>(x, out);
}

// round 15
// speedup vs baseline: 1.1463x; 1.0308x over previous
#include <cuda_runtime.h>

// Fixed problem shape
#define NMOL   256
#define NATOM  512
#define KNB    32
#define NTOT   (NMOL * NATOM)            // 131072 atoms
#define EDG    ((size_t)NTOT * KNB)      // 4194304 edges
#define TPB    128                       // 1 thread per atom
#define INFK32 0xFFFFFFFFu
#define ACCB   0x3F7FFFFFu               // (b-1) < ACCB  <=>  0 < d2 < 1
#define LOB    0x3F199999u               // (b-1) < LOB   <=>  0 < d2 < 0.6f
#define HISKIP 0x3F19999Au               // root k below this => no hi key can enter

typedef unsigned long long u64;
typedef unsigned int       u32;
typedef unsigned short     u16;

// smem: hk u32[33*TPB]=16896 + hj u16[33*TPB]=8448 + pos 6144 = 31488 B
// -> 7 blocks/SM, grid 1024 over 1036 slots: 1 wave, 1.2% imbalance.
#define HK_BYTES (33 * TPB * 4)
#define HJ_BYTES (33 * TPB * 2)
#define SMEM_BYTES (HK_BYTES + HJ_BYTES + NATOM * 12)

__device__ __forceinline__ u64 pk2(u32 lo, u32 hi) {
    u64 r; asm("mov.b64 %0, {%1, %2};" : "=l"(r) : "r"(lo), "r"(hi)); return r;
}
__device__ __forceinline__ void upk2(u64 v, u32& lo, u32& hi) {
    asm("mov.b64 {%0, %1}, %2;" : "=r"(lo), "=r"(hi) : "l"(v));
}
__device__ __forceinline__ u64 addx2(u64 a, u64 b) {
    u64 r; asm("add.rn.f32x2 %0, %1, %2;" : "=l"(r) : "l"(a), "l"(b)); return r;
}
__device__ __forceinline__ u64 mulx2(u64 a, u64 b) {
    u64 r; asm("mul.rn.f32x2 %0, %1, %2;" : "=l"(r) : "l"(a), "l"(b)); return r;
}
__device__ __forceinline__ u64 fmax2(u64 a, u64 b, u64 c) {
    u64 r; asm("fma.rn.f32x2 %0, %1, %2, %3;" : "=l"(r) : "l"(a), "l"(b), "l"(c)); return r;
}
__device__ __forceinline__ float sqrt_ap(float v) {
    float r; asm("sqrt.approx.f32 %0, %1;" : "=f"(r) : "f"(v)); return r;
}

// d2 with FMA contraction — used CONSISTENTLY in fill and stream (matches the
// packed fma.rn.f32x2 phase-1 formula bit-for-bit on the same inputs).
__device__ __forceinline__ float d2fma(float jx, float jy, float jz,
                                       float nx, float ny, float nz)
{
    const float dx = __fadd_rn(jx, nx);
    const float dy = __fadd_rn(jy, ny);
    const float dz = __fadd_rn(jz, nz);
    return __fmaf_rn(dz, dz, __fmaf_rn(dy, dy, __fmul_rn(dx, dx)));
}

// Exact lexicographic (d2bits, j) order (asc d2, then asc j).
__device__ __forceinline__ bool ltp(u32 ka, u32 ja, u32 kb, u32 jb) {
    return (ka < kb) || (ka == kb && ja < jb);
}
__device__ __forceinline__ bool gtp(u32 ka, u32 ja, u32 kb, u32 jb) {
    return (ka > kb) || (ka == kb && ja > jb);
}

// Strided heap slots (R10 layout: shift-add addressing, no IMAD).
#define HK(q) hk[(q) * TPB + tid]
#define HJ(q) hj[(q) * TPB + tid]

// 4-ary max-heap sift-down, fixed size 32 (slot 32 = pad (0,0), never wins).
// Depth <= 3: fully unrolled. Updates (rk, rj) when the root slot changes.
__device__ __forceinline__ void siftd(u32* hk, u16* hj, int tid,
                                      int p, u32 k, u32 j, u32& rk, u32& rj)
{
    if (p == 0) { rk = k; rj = j; }               // provisional root
    #pragma unroll
    for (int lvl = 0; lvl < 3; ++lvl) {
        const int l = 4 * p + 1;
        if (l > 31) break;                        // leaf
        const u32 k0 = HK(l),     j0 = HJ(l);
        const u32 k1 = HK(l + 1), j1 = HJ(l + 1);
        const u32 k2 = HK(l + 2), j2 = HJ(l + 2);
        const u32 k3 = HK(l + 3), j3 = HJ(l + 3); // p==7 -> slot 32 pad (0,0)
        u32 ak, aj, bk, bj; int ai, bi;
        if (gtp(k1, j1, k0, j0)) { ak = k1; aj = j1; ai = l + 1; }
        else                     { ak = k0; aj = j0; ai = l;     }
        if (gtp(k3, j3, k2, j2)) { bk = k3; bj = j3; bi = l + 3; }
        else                     { bk = k2; bj = j2; bi = l + 2; }
        u32 mk, mj; int mi;
        if (gtp(bk, bj, ak, aj)) { mk = bk; mj = bj; mi = bi; }
        else                     { mk = ak; mj = aj; mi = ai; }
        if (!gtp(mk, mj, k, j)) break;
        HK(p) = mk; HJ(p) = (u16)mj;
        if (p == 0) { rk = mk; rj = mj; }
        p = mi;
    }
    HK(p) = k; HJ(p) = (u16)j;
}

// Stream one u64 mask word through the full heap (replace-root when better).
__device__ __forceinline__ void stream_word(
    u32* hk, u16* hj, int tid, u64 m, int w,
    const float* sx, const float* sy, const float* sz,
    float nx, float ny, float nz, u32& rk, u32& rj)
{
    #pragma unroll 1
    while (m) {
        const int b = __ffsll(m) - 1;
        m &= m - 1;
        const int j = (w << 6) + b;
        const float d2 = d2fma(sx[j], sy[j], sz[j], nx, ny, nz);
        const u32 kb = __float_as_uint(d2);
        if (ltp(kb, (u32)j, rk, rj))
            siftd(hk, hj, tid, 0, kb, (u32)j, rk, rj);
    }
}

__global__ void __launch_bounds__(TPB, 7)
topo_kernel(const float* __restrict__ x, float* __restrict__ out)
{
    extern __shared__ char dsm[];
    u32*   hk = (u32*)dsm;
    u16*   hj = (u16*)(dsm + HK_BYTES);
    float* sx = (float*)(dsm + HK_BYTES + HJ_BYTES);    // 16B-aligned (8448%16==0)
    float* sy = sx + NATOM;
    float* sz = sy + NATOM;

    const int tid     = threadIdx.x;
    const int gatom   = blockIdx.x * TPB + tid;
    const int molbase = gatom & ~(NATOM - 1);
    const int i       = gatom & (NATOM - 1);

    for (int a = tid; a < NATOM; a += TPB) {
        const float* p = x + (size_t)(molbase + a) * 3;
        sx[a] = p[0]; sy[a] = p[1]; sz[a] = p[2];
    }
    __syncthreads();

    const float px = sx[i], py = sy[i], pz = sz[i];
    const float nx = -px,   ny = -py,   nz = -pz;
    const u64 npx = pk2(__float_as_uint(nx), __float_as_uint(nx));
    const u64 npy = pk2(__float_as_uint(ny), __float_as_uint(ny));
    const u64 npz = pk2(__float_as_uint(nz), __float_as_uint(nz));

    const u64* sx2 = reinterpret_cast<const u64*>(sx);
    const u64* sy2 = reinterpret_cast<const u64*>(sy);
    const u64* sz2 = reinterpret_cast<const u64*>(sz);

    // ---- Phase 1: distances 2-at-a-time with packed FMA (6 x2-ops/pair).
    //      u64 masks: mlo = near (0<d2<0.6), mhi = far (0.6<=d2<1). ----
    u64 mlo8[8], mhi8[8];

    #pragma unroll 1
    for (int w = 0; w < 8; ++w) {
        u64 ma = 0, ml = 0;
        #pragma unroll
        for (int s = 0; s < 32; ++s) {
            const int t  = w * 32 + s;
            const u64 dx = addx2(sx2[t], npx);
            const u64 dy = addx2(sy2[t], npy);
            const u64 dz = addx2(sz2[t], npz);
            const u64 d2 = fmax2(dz, dz, fmax2(dy, dy, mulx2(dx, dx)));
            u32 b0, b1; upk2(d2, b0, b1);
            if (b0 - 1u < ACCB) ma |= (1ull << (2 * s));
            if (b1 - 1u < ACCB) ma |= (2ull << (2 * s));
            if (b0 - 1u < LOB)  ml |= (1ull << (2 * s));
            if (b1 - 1u < LOB)  ml |= (2ull << (2 * s));
        }
        mhi8[w] = ma ^ ml;
        mlo8[w] = ml;
    }

    // ---- Heap prefill (INFK32 = invalid; lanes with <32 neighbors keep some) ----
    #pragma unroll
    for (int q = 0; q < 32; ++q) { HK(q) = INFK32; HJ(q) = 0xFFFFu; }
    HK(32) = 0; HJ(32) = 0;                       // pad child: never promoted

    // ---- Stage A: append-only fill, near candidates first, then far. ----
    int hc = 0;
    int wr = 8; u64 mr = 0;                       // lo resume point
    int wh = 8; u64 mh = 0;                       // hi resume point

    #pragma unroll 1
    for (int w = 0; w < 8; ++w) {
        u64 m = mlo8[w];
        #pragma unroll 1
        while (m && hc < 32) {
            const int b = __ffsll(m) - 1;
            m &= m - 1;
            const int j = (w << 6) + b;
            const float d2 = d2fma(sx[j], sy[j], sz[j], nx, ny, nz);
            HK(hc) = __float_as_uint(d2); HJ(hc) = (u16)j;
            ++hc;
        }
        if (m) { wr = w; mr = m; break; }         // heap filled, lo bits remain
    }

    if (hc == 32) {
        wh = 0; mh = mhi8[0];                     // entire hi pass pending
    } else {
        #pragma unroll 1
        for (int w = 0; w < 8; ++w) {
            u64 m = mhi8[w];
            #pragma unroll 1
            while (m && hc < 32) {
                const int b = __ffsll(m) - 1;
                m &= m - 1;
                const int j = (w << 6) + b;
                const float d2 = d2fma(sx[j], sy[j], sz[j], nx, ny, nz);
                HK(hc) = __float_as_uint(d2); HJ(hc) = (u16)j;
                ++hc;
            }
            if (m) { wh = w; mh = m; break; }
        }
    }

    // ---- Floyd heapify: uniform 8 sift-downs (4-ary, depth <= 3) ----
    u32 rk = INFK32, rj = 0xFFFFu;
    #pragma unroll 1
    for (int p = 7; p >= 0; --p)
        siftd(hk, hj, tid, p, HK(p), HJ(p), rk, rj);  // p==0 call yields true root

    // ---- Stage B: stream remainders. Near first; far pass skipped
    //      algebraically once rk < 0x3F19999A (no far key can beat root). ----
    if (wr < 8) {
        stream_word(hk, hj, tid, mr, wr, sx, sy, sz, nx, ny, nz, rk, rj);
        #pragma unroll 1
        for (int w = wr + 1; w < 8; ++w)
            stream_word(hk, hj, tid, mlo8[w], w, sx, sy, sz, nx, ny, nz, rk, rj);
    }
    if (wh < 8) {
        u64 m0 = (rk < HISKIP) ? 0ull : mh;
        stream_word(hk, hj, tid, m0, wh, sx, sy, sz, nx, ny, nz, rk, rj);
        #pragma unroll 1
        for (int w = wh + 1; w < 8; ++w) {
            u64 m = (rk < HISKIP) ? 0ull : mhi8[w];
            stream_word(hk, hj, tid, m, w, sx, sy, sz, nx, ny, nz, rk, rj);
        }
    }

    // ---- Heapsort: 31 uniform pops (INFK32s land in the tail slots),
    //      leaves slots 0..31 ascending by (d2bits, j). ----
    #pragma unroll 1
    for (int size = 31; size >= 1; --size) {
        const u32 tk = HK(0); const u32 tj = HJ(0);
        u32 k = HK(size), j = HJ(size);
        HK(size) = tk; HJ(size) = (u16)tj;
        int p = 0;
        #pragma unroll
        for (int lvl = 0; lvl < 3; ++lvl) {
            const int l = 4 * p + 1;
            if (l >= size) break;
            const u32 k0 = HK(l),                          j0 = HJ(l);
            const u32 k1 = (l + 1 < size) ? HK(l + 1) : 0, j1 = (l + 1 < size) ? HJ(l + 1) : 0;
            const u32 k2 = (l + 2 < size) ? HK(l + 2) : 0, j2 = (l + 2 < size) ? HJ(l + 2) : 0;
            const u32 k3 = (l + 3 < size) ? HK(l + 3) : 0, j3 = (l + 3 < size) ? HJ(l + 3) : 0;
            u32 ak, aj, bk, bj; int ai, bi;
            if (gtp(k1, j1, k0, j0)) { ak = k1; aj = j1; ai = l + 1; }
            else                     { ak = k0; aj = j0; ai = l;     }
            if (gtp(k3, j3, k2, j2)) { bk = k3; bj = j3; bi = l + 3; }
            else                     { bk = k2; bj = j2; bi = l + 2; }
            u32 mk, mj; int mi;
            if (gtp(bk, bj, ak, aj)) { mk = bk; mj = bj; mi = bi; }
            else                     { mk = ak; mj = aj; mi = ai; }
            if (!gtp(mk, mj, k, j)) break;
            HK(p) = mk; HJ(p) = (u16)mj;
            p = mi;
        }
        HK(p) = k; HJ(p) = (u16)j;
    }

    // ---- Phase 3: emit, per-atom contiguous -> all float4 stores. ----
    float* obi  = out + (size_t)gatom * KNB;
    float* obj  = out + EDG + (size_t)gatom * KNB;
    float* ovec = out + 2 * EDG + (size_t)gatom * (3 * KNB);
    float* odst = out + 5 * EDG + (size_t)gatom * KNB;
    float* oval = out + 6 * EDG + (size_t)gatom * KNB;

    const float fgi = (float)gatom;

    #pragma unroll
    for (int qb = 0; qb < KNB / 4; ++qb) {
        float bi4[4], bj4[4], dd4[4], vv4[4], vec12[12];
        #pragma unroll
        for (int u = 0; u < 4; ++u) {
            const int  s   = qb * 4 + u;
            const u32  d2b = HK(s);
            const bool ok  = (d2b != INFK32);     // real keys <= 0x3F7FFFFF
            const int  j   = (int)HJ(s) & (NATOM - 1);
            const float dx = __fadd_rn(sx[j], nx);
            const float dy = __fadd_rn(sy[j], ny);
            const float dz = __fadd_rn(sz[j], nz);
            vec12[u * 3 + 0] = ok ? dx : 0.0f;
            vec12[u * 3 + 1] = ok ? dy : 0.0f;
            vec12[u * 3 + 2] = ok ? dz : 0.0f;
            bi4[u] = ok ? fgi : -1.0f;
            bj4[u] = ok ? (float)(molbase + j) : -1.0f;
            dd4[u] = ok ? sqrt_ap(__uint_as_float(d2b)) : 0.0f;
            vv4[u] = ok ? 1.0f : 0.0f;
        }
        *(float4*)(obi  + qb * 4)      = make_float4(bi4[0], bi4[1], bi4[2], bi4[3]);
        *(float4*)(obj  + qb * 4)      = make_float4(bj4[0], bj4[1], bj4[2], bj4[3]);
        *(float4*)(odst + qb * 4)      = make_float4(dd4[0], dd4[1], dd4[2], dd4[3]);
        *(float4*)(oval + qb * 4)      = make_float4(vv4[0], vv4[1], vv4[2], vv4[3]);
        *(float4*)(ovec + qb * 12 + 0) = make_float4(vec12[0], vec12[1], vec12[2],  vec12[3]);
        *(float4*)(ovec + qb * 12 + 4) = make_float4(vec12[4], vec12[5], vec12[6],  vec12[7]);
        *(float4*)(ovec + qb * 12 + 8) = make_float4(vec12[8], vec12[9], vec12[10], vec12[11]);
    }
}

extern "C" void kernel_launch(void* const* d_in, const int* in_sizes, int n_in,
                              void* d_out, int out_size)
{
    const float* x   = (const float*)d_in[0];
    float*       out = (float*)d_out;

    cudaFuncSetAttribute(topo_kernel, cudaFuncAttributeMaxDynamicSharedMemorySize,
                         SMEM_BYTES);
    topo_kernel<<<NTOT / TPB, TPB, SMEM_BYTES>>>(x, out);
}